// round 3
// baseline (speedup 1.0000x reference)
#include <cuda_runtime.h>

// Problem constants
#define T_STEPS 1024
#define Hn      100
#define Kpad    104   // k padded to 4*26
#define BB      4     // batch rows per block
#define KC      4     // k-split factor (threads per hidden unit)
#define KK      26    // padded k elements per thread (Kpad / KC)
#define NPAIR   13    // KK/2 f32x2 weight pairs per gate
#define NTHREADS 416  // 104 n-slots * 4 kc (13 warps; n>=100 inert)
#define NWARPS  13

typedef unsigned long long ull;

// ---------- f32x2 packed-math helpers ----------
__device__ __forceinline__ ull pack2(float lo, float hi) {
    ull r; asm("mov.b64 %0, {%1, %2};" : "=l"(r) : "f"(lo), "f"(hi)); return r;
}
__device__ __forceinline__ void unpack2(ull v, float& lo, float& hi) {
    asm("mov.b64 {%0, %1}, %2;" : "=f"(lo), "=f"(hi) : "l"(v));
}
__device__ __forceinline__ ull ffma2(ull a, ull b, ull c) {
    ull d; asm("fma.rn.f32x2 %0, %1, %2, %3;" : "=l"(d) : "l"(a), "l"(b), "l"(c)); return d;
}
__device__ __forceinline__ ull fadd2(ull a, ull b) {
    ull d; asm("add.rn.f32x2 %0, %1, %2;" : "=l"(d) : "l"(a), "l"(b)); return d;
}

// ---------- fast transcendentals (MUFU, ~1e-6 rel err) ----------
__device__ __forceinline__ float ex2a(float x) {
    float y; asm("ex2.approx.ftz.f32 %0, %1;" : "=f"(y) : "f"(x)); return y;
}
__device__ __forceinline__ float rcpa(float x) {
    float y; asm("rcp.approx.ftz.f32 %0, %1;" : "=f"(y) : "f"(x)); return y;
}
__device__ __forceinline__ float sigm(float x) {
    return rcpa(1.0f + ex2a(-1.4426950408889634f * x));
}
__device__ __forceinline__ float tanhx(float x) {
    return fmaf(2.0f, rcpa(1.0f + ex2a(-2.8853900817779268f * x)), -1.0f);
}

// Interleaved h layout within one batch row of Kpad floats:
//   k = kc*26 + r;  r<24:  idx = (r/4)*16 + kc*4 + (r%4)
//                   r>=24: idx = 96 + kc*2 + (r-24)
// => thread kc loads 6 x float4 at idx j*16+kc*4 (j=0..5) and 1 x float2 at
//    96+kc*2. Inside a warp the 4 kc streams at the same j are ADJACENT
//    float4s (one 64B run -> single line -> 1 wavefront, broadcast across n).
__device__ __forceinline__ int h_idx_of_k(int k) {
    int kc = k / KK, r = k % KK;
    return (r < 24) ? ((r >> 2) * 16 + kc * 4 + (r & 3))
                    : (96 + kc * 2 + (r - 24));
}

// Thread layout: tid = n*4 + kc (butterfly partners at lane xor 1, 2).
__global__ void __launch_bounds__(NTHREADS, 1)
lstm_persistent_kernel(const float* __restrict__ input,   // [512][1024]
                       const float* __restrict__ W_ih,    // [400]
                       const float* __restrict__ W_hh,    // [400][100]
                       const float* __restrict__ b_ih,    // [400]
                       const float* __restrict__ b_hh,    // [400]
                       const float* __restrict__ W_out,   // [100]
                       const float* __restrict__ b_out,   // [1]
                       float* __restrict__ out)           // [512][1024]
{
    __shared__ __align__(16) float h2[2][BB][Kpad];   // double buffered
    __shared__ float outpart[2][NWARPS * 4];

    const int tid  = threadIdx.x;
    const int n    = tid >> 2;
    const int kc   = tid & 3;
    const int lane = tid & 31;
    const int wid  = tid >> 5;
    const bool valid = (n < Hn);
    const int bbase = blockIdx.x * BB;

    // ---- register-stationary recurrent weights: w[g][j]=(w_k0,w_k0+1) ----
    ull w[4][NPAIR];
    float wih_i = 0.f, wih_f = 0.f, wih_g = 0.f, wih_o = 0.f;
    float bi = 0.f, bf = 0.f, bg = 0.f, bo = 0.f, wout = 0.f;
    #pragma unroll
    for (int g = 0; g < 4; ++g) {
        const float* row = W_hh + (g * Hn + (valid ? n : 0)) * Hn;
        #pragma unroll
        for (int j = 0; j < NPAIR; ++j) {
            const int k0 = kc * KK + 2 * j;
            float f0 = (valid && k0     < Hn) ? row[k0]     : 0.0f;
            float f1 = (valid && k0 + 1 < Hn) ? row[k0 + 1] : 0.0f;
            w[g][j] = pack2(f0, f1);
        }
    }
    if (valid) {
        wih_i = W_ih[0 * Hn + n];
        wih_f = W_ih[1 * Hn + n];
        wih_g = W_ih[2 * Hn + n];
        wih_o = W_ih[3 * Hn + n];
        bi = b_ih[0 * Hn + n] + b_hh[0 * Hn + n];
        bf = b_ih[1 * Hn + n] + b_hh[1 * Hn + n];
        bg = b_ih[2 * Hn + n] + b_hh[2 * Hn + n];
        bo = b_ih[3 * Hn + n] + b_hh[3 * Hn + n];
        wout = W_out[n];
    }
    const float bout = b_out[0];

    // zero both h buffers
    for (int i = tid; i < 2 * BB * Kpad; i += NTHREADS)
        (&h2[0][0][0])[i] = 0.0f;

    float c_state = 0.0f;
    const float* __restrict__ xptr = input + (bbase + kc) * T_STEPS;
    // write slot: thread (n, kc) produces h[n] for batch b=kc; hidden n acts
    // as k = n in the next step's matvec -> interleaved slot h_idx_of_k(n).
    float* const hw0 = &h2[0][kc][0] + h_idx_of_k(n);

    __syncthreads();

    for (int t = 0; t < T_STEPS; ++t) {
        const int p = t & 1;
        const float xv = xptr[t];
        const float* const hbuf = &h2[p][0][0];

        float gi_r = 0.f, gf_r = 0.f, gg_r = 0.f, go_r = 0.f;

        // two batch-pair halves: (b0,b1) then (b2,b3)
        #pragma unroll
        for (int half = 0; half < 2; ++half) {
            ull acc[4][2];
            #pragma unroll
            for (int g = 0; g < 4; ++g) { acc[g][0] = 0ULL; acc[g][1] = 0ULL; }

            #pragma unroll
            for (int bq = 0; bq < 2; ++bq) {
                const float* rowp = hbuf + (half * 2 + bq) * Kpad;
                const ulonglong2* v4 =
                    reinterpret_cast<const ulonglong2*>(rowp + kc * 4);
                #pragma unroll
                for (int j = 0; j < 6; ++j) {
                    // idx = j*16 + kc*4 : two k-pairs (4j,4j+1), (4j+2,4j+3)
                    const ulonglong2 hp = v4[j * 4];
                    #pragma unroll
                    for (int g = 0; g < 4; ++g) {
                        acc[g][bq] = ffma2(w[g][2 * j],     hp.x, acc[g][bq]);
                        acc[g][bq] = ffma2(w[g][2 * j + 1], hp.y, acc[g][bq]);
                    }
                }
                // tail pair: k = 24,25 of this chunk at idx 96 + kc*2
                const ull ht = *reinterpret_cast<const ull*>(rowp + 96 + kc * 2);
                #pragma unroll
                for (int g = 0; g < 4; ++g)
                    acc[g][bq] = ffma2(w[g][NPAIR - 1], ht, acc[g][bq]);
            }

            // butterfly-reduce across the 4 kc lanes (packed adds)
            #pragma unroll
            for (int off = 1; off <= 2; off <<= 1) {
                #pragma unroll
                for (int g = 0; g < 4; ++g) {
                    acc[g][0] = fadd2(acc[g][0],
                                      __shfl_xor_sync(0xffffffffu, acc[g][0], off));
                    acc[g][1] = fadd2(acc[g][1],
                                      __shfl_xor_sync(0xffffffffu, acc[g][1], off));
                }
            }

            // lanes with kc>>1 == half own batch b = kc: take acc[g][kc&1]
            if ((kc >> 1) == half) {
                const int s = kc & 1;
                float lo, hi;
                unpack2(s ? acc[0][1] : acc[0][0], lo, hi); gi_r = lo + hi;
                unpack2(s ? acc[1][1] : acc[1][0], lo, hi); gf_r = lo + hi;
                unpack2(s ? acc[2][1] : acc[2][0], lo, hi); gg_r = lo + hi;
                unpack2(s ? acc[3][1] : acc[3][0], lo, hi); go_r = lo + hi;
            }
        }

        // ---- elementwise gate math for (n, b=kc) ----
        const float gi = fmaf(xv, wih_i, gi_r + bi);
        const float gf = fmaf(xv, wih_f, gf_r + bf);
        const float gg = fmaf(xv, wih_g, gg_r + bg);
        const float go = fmaf(xv, wih_o, go_r + bo);

        const float ig = sigm(gi);
        const float fg = sigm(gf);
        const float gc = tanhx(gg);
        const float og = sigm(go);
        c_state = fmaf(fg, c_state, ig * gc);
        const float h_ = og * tanhx(c_state);

        // publish h into the other buffer (interleaved slot)
        hw0[(p ^ 1) * (BB * Kpad)] = h_;

        // ---- output projection: reduce h*W_out over n ----
        float po = h_ * wout;   // inert lanes contribute exactly 0
        #pragma unroll
        for (int off = 4; off < 32; off <<= 1)
            po += __shfl_xor_sync(0xffffffffu, po, off);
        if (lane < 4) outpart[p][wid * 4 + lane] = po;

        __syncthreads();

        if (tid < BB) {
            float s = bout;
            #pragma unroll
            for (int wv = 0; wv < NWARPS; ++wv) s += outpart[p][wv * 4 + tid];
            out[(bbase + tid) * T_STEPS + t] = s;
        }
    }
}

extern "C" void kernel_launch(void* const* d_in, const int* in_sizes, int n_in,
                              void* d_out, int out_size) {
    (void)in_sizes; (void)n_in; (void)out_size;
    const float* input = (const float*)d_in[0];
    const float* W_ih  = (const float*)d_in[1];
    const float* W_hh  = (const float*)d_in[2];
    const float* b_ih  = (const float*)d_in[3];
    const float* b_hh  = (const float*)d_in[4];
    const float* W_out = (const float*)d_in[5];
    const float* b_out = (const float*)d_in[6];
    float* out = (float*)d_out;

    lstm_persistent_kernel<<<512 / BB, NTHREADS>>>(
        input, W_ih, W_hh, b_ih, b_hh, W_out, b_out, out);
}

// round 6
// speedup vs baseline: 1.3517x; 1.3517x over previous
#include <cuda_runtime.h>

// Problem constants
#define T_STEPS 1024
#define Hn      100
#define BB      4     // batch rows per block
#define KC      4     // k-split (threads per hidden unit); 25 k each, exact
#define NJ      12    // k-pairs per thread (24 k) + 1 scalar tail
#define NTHREADS 416  // 104 n-slots * 4 kc (13 warps; n>=100 inert)
#define NWARPS  13

typedef unsigned long long ull;

// ---------- f32x2 packed-math helpers ----------
__device__ __forceinline__ ull pack2(float lo, float hi) {
    ull r; asm("mov.b64 %0, {%1, %2};" : "=l"(r) : "f"(lo), "f"(hi)); return r;
}
__device__ __forceinline__ void unpack2(ull v, float& lo, float& hi) {
    asm("mov.b64 {%0, %1}, %2;" : "=f"(lo), "=f"(hi) : "l"(v));
}
__device__ __forceinline__ ull ffma2(ull a, ull b, ull c) {
    ull d; asm("fma.rn.f32x2 %0, %1, %2, %3;" : "=l"(d) : "l"(a), "l"(b), "l"(c)); return d;
}
__device__ __forceinline__ ull fadd2(ull a, ull b) {
    ull d; asm("add.rn.f32x2 %0, %1, %2;" : "=l"(d) : "l"(a), "l"(b)); return d;
}

// ---------- fast transcendentals (MUFU, ~1e-6 rel err) ----------
__device__ __forceinline__ float ex2a(float x) {
    float y; asm("ex2.approx.ftz.f32 %0, %1;" : "=f"(y) : "f"(x)); return y;
}
__device__ __forceinline__ float rcpa(float x) {
    float y; asm("rcp.approx.ftz.f32 %0, %1;" : "=f"(y) : "f"(x)); return y;
}
__device__ __forceinline__ float sigm(float x) {
    return rcpa(1.0f + ex2a(-1.4426950408889634f * x));
}
__device__ __forceinline__ float tanhx(float x) {
    return fmaf(2.0f, rcpa(1.0f + ex2a(-2.8853900817779268f * x)), -1.0f);
}

// Interleaved h layout inside one batch row of 100 floats:
//   k = q*25 + r (q = k-quarter 0..3):
//     r < 24 : idx = (r/4)*16 + q*4 + (r%4)   (6 float4 chunks per quarter)
//     r == 24: idx = 96 + q                    (scalar tail)
// => thread with kc=q reads 6 float4 at idx j*16+q*4 plus 1 float at 96+q.
//    Within one warp LDS.128 the 4 q streams are ADJACENT 16B chunks of one
//    64B run -> broadcast-dedup to a single wavefront.
__device__ __forceinline__ int h_idx_of_k(int k) {
    int q = k / 25, r = k % 25;
    return (r < 24) ? ((r >> 2) * 16 + q * 4 + (r & 3)) : (96 + q);
}

// Thread layout: tid = n*4 + kc. Lane owns batch b = kc after the trimmed
// butterfly (c-state in a register).
// NOTE: 13 warps -> 4 on one SMSP -> per-thread reg cap is 512/4 = 128.
// __launch_bounds__(416,1) pins ptxas at 128; ~20 read-only weight regs spill
// to local (coalesced LDL reloads) — structurally unavoidable at this width.
__global__ void __launch_bounds__(NTHREADS, 1)
lstm_persistent_kernel(const float* __restrict__ input,   // [512][1024]
                       const float* __restrict__ W_ih,    // [400]
                       const float* __restrict__ W_hh,    // [400][100]
                       const float* __restrict__ b_ih,    // [400]
                       const float* __restrict__ b_hh,    // [400]
                       const float* __restrict__ W_out,   // [100]
                       const float* __restrict__ b_out,   // [1]
                       float* __restrict__ out)           // [512][1024]
{
    __shared__ __align__(16) float h2[2][BB][Hn];   // double buffered
    __shared__ float outpart[2][NWARPS * 4];

    const int tid  = threadIdx.x;
    const int n    = tid >> 2;
    const int kc   = tid & 3;
    const int lane = tid & 31;
    const int wid  = tid >> 5;
    const bool valid = (n < Hn);
    const int bbase = blockIdx.x * BB;
    const int side = kc >> 1;        // 0 -> owns batches {0,1}, 1 -> {2,3}
    const int par  = kc & 1;

    // ---- register-stationary recurrent weights (k-paired) ----
    ull  w[4][NJ];     // (w_k, w_k+1) for k = kc*25 + 2j
    float wt[4];       // tail weight k = kc*25 + 24
    ull b01 = 0, b23 = 0, wihif = 0, wihgo = 0;
    float wout = 0.f;
    #pragma unroll
    for (int g = 0; g < 4; ++g) {
        const float* row = W_hh + (g * Hn + (valid ? n : 0)) * Hn;
        #pragma unroll
        for (int j = 0; j < NJ; ++j) {
            const int k0 = kc * 25 + 2 * j;
            w[g][j] = valid ? pack2(row[k0], row[k0 + 1]) : 0ULL;
        }
        wt[g] = valid ? row[kc * 25 + 24] : 0.0f;
    }
    if (valid) {
        wihif = pack2(W_ih[0 * Hn + n], W_ih[1 * Hn + n]);
        wihgo = pack2(W_ih[2 * Hn + n], W_ih[3 * Hn + n]);
        b01 = pack2(b_ih[0 * Hn + n] + b_hh[0 * Hn + n],
                    b_ih[1 * Hn + n] + b_hh[1 * Hn + n]);
        b23 = pack2(b_ih[2 * Hn + n] + b_hh[2 * Hn + n],
                    b_ih[3 * Hn + n] + b_hh[3 * Hn + n]);
        wout = W_out[n];
    }
    const float bout = b_out[0];

    // zero both h buffers
    for (int i = tid; i < 2 * BB * Hn; i += NTHREADS)
        (&h2[0][0][0])[i] = 0.0f;

    float c_state = 0.0f;
    const float* __restrict__ xptr = input + (bbase + kc) * T_STEPS;
    // write slot: thread (n, kc) publishes h[n] for batch kc; it is read next
    // step as k = n -> interleaved slot h_idx_of_k(n).
    float* const hw0 = &h2[0][kc][0] + (valid ? h_idx_of_k(n) : 0);

    __syncthreads();

    for (int t = 0; t < T_STEPS; ++t) {
        const int p = t & 1;
        const float xv = xptr[t];
        const float* const hbuf = &h2[p][0][0];

        // per-batch gate partials packed as (i,f) and (g,o)
        ull q01[4], q23[4];

        // two batch-pair passes to bound accumulator registers
        #pragma unroll
        for (int bp = 0; bp < 2; ++bp) {
            ull a[4][2];
            #pragma unroll
            for (int g = 0; g < 4; ++g) { a[g][0] = 0ULL; a[g][1] = 0ULL; }
            float ht[2];

            #pragma unroll
            for (int bq = 0; bq < 2; ++bq) {
                const float* rowp = hbuf + (bp * 2 + bq) * Hn;
                const ulonglong2* v4 =
                    reinterpret_cast<const ulonglong2*>(rowp + kc * 4);
                #pragma unroll
                for (int j = 0; j < 6; ++j) {
                    const ulonglong2 hp = v4[j * 4];  // k-pairs 2j*2, 2j*2+1
                    #pragma unroll
                    for (int g = 0; g < 4; ++g) {
                        a[g][bq] = ffma2(w[g][2 * j],     hp.x, a[g][bq]);
                        a[g][bq] = ffma2(w[g][2 * j + 1], hp.y, a[g][bq]);
                    }
                }
                ht[bq] = rowp[96 + kc];  // tail k
            }

            // fold k-pair partials to scalars, add tail, pack by gate pairs
            #pragma unroll
            for (int bq = 0; bq < 2; ++bq) {
                float s0, s1, s2, s3, lo, hi;
                unpack2(a[0][bq], lo, hi); s0 = fmaf(wt[0], ht[bq], lo + hi);
                unpack2(a[1][bq], lo, hi); s1 = fmaf(wt[1], ht[bq], lo + hi);
                unpack2(a[2][bq], lo, hi); s2 = fmaf(wt[2], ht[bq], lo + hi);
                unpack2(a[3][bq], lo, hi); s3 = fmaf(wt[3], ht[bq], lo + hi);
                q01[bp * 2 + bq] = pack2(s0, s1);
                q23[bp * 2 + bq] = pack2(s2, s3);
            }
        }

        // ---- trimmed butterfly: 6 ull shuffles reduce all 4 batches ----
        // Round 1 (xor 2): send partner-side batches, keep own side.
        const ull s1 = side ? q01[0] : q01[2];
        const ull s2 = side ? q01[1] : q01[3];
        const ull s3 = side ? q23[0] : q23[2];
        const ull s4 = side ? q23[1] : q23[3];
        const ull r1 = __shfl_xor_sync(0xffffffffu, s1, 2);
        const ull r2 = __shfl_xor_sync(0xffffffffu, s2, 2);
        const ull r3 = __shfl_xor_sync(0xffffffffu, s3, 2);
        const ull r4 = __shfl_xor_sync(0xffffffffu, s4, 2);
        const ull u01a = fadd2(side ? q01[2] : q01[0], r1);  // batch 2*side
        const ull u01b = fadd2(side ? q01[3] : q01[1], r2);  // batch 2*side+1
        const ull u23a = fadd2(side ? q23[2] : q23[0], r3);
        const ull u23b = fadd2(side ? q23[3] : q23[1], r4);
        // Round 2 (xor 1): send partner's batch, keep mine (batch = kc).
        const ull t01 = par ? u01a : u01b;
        const ull t23 = par ? u23a : u23b;
        const ull w01r = __shfl_xor_sync(0xffffffffu, t01, 1);
        const ull w23r = __shfl_xor_sync(0xffffffffu, t23, 1);
        ull G01 = fadd2(par ? u01b : u01a, w01r);
        ull G23 = fadd2(par ? u23b : u23a, w23r);

        // ---- gates for (n, b = kc): packed bias + input projection ----
        const ull xv2 = pack2(xv, xv);
        G01 = ffma2(xv2, wihif, fadd2(G01, b01));
        G23 = ffma2(xv2, wihgo, fadd2(G23, b23));
        float gi, gf, gg, go;
        unpack2(G01, gi, gf);
        unpack2(G23, gg, go);

        const float ig = sigm(gi);
        const float fg = sigm(gf);
        const float gc = tanhx(gg);
        const float og = sigm(go);
        c_state = fmaf(fg, c_state, ig * gc);
        const float h_ = og * tanhx(c_state);

        // publish h into the other buffer (interleaved slot)
        if (valid) hw0[(p ^ 1) * (BB * Hn)] = h_;

        // ---- output projection: reduce h*W_out over n within warp ----
        float po = h_ * wout;   // inert lanes contribute exactly 0
        #pragma unroll
        for (int off = 4; off < 32; off <<= 1)
            po += __shfl_xor_sync(0xffffffffu, po, off);
        if (lane < 4) outpart[p][wid * 4 + lane] = po;

        __syncthreads();

        if (tid < BB) {
            float s = bout;
            #pragma unroll
            for (int wv = 0; wv < NWARPS; ++wv) s += outpart[p][wv * 4 + tid];
            out[(bbase + tid) * T_STEPS + t] = s;
        }
    }
}

extern "C" void kernel_launch(void* const* d_in, const int* in_sizes, int n_in,
                              void* d_out, int out_size) {
    (void)in_sizes; (void)n_in; (void)out_size;
    const float* input = (const float*)d_in[0];
    const float* W_ih  = (const float*)d_in[1];
    const float* W_hh  = (const float*)d_in[2];
    const float* b_ih  = (const float*)d_in[3];
    const float* b_hh  = (const float*)d_in[4];
    const float* W_out = (const float*)d_in[5];
    const float* b_out = (const float*)d_in[6];
    float* out = (float*)d_out;

    lstm_persistent_kernel<<<512 / BB, NTHREADS>>>(
        input, W_ih, W_hh, b_ih, b_hh, W_out, b_out, out);
}

// round 7
// speedup vs baseline: 1.3971x; 1.0336x over previous
#include <cuda_runtime.h>

// Problem constants
#define T_STEPS 1024
#define Hn      100
#define HPAD    104   // padded hidden (4 junk slots for inert lanes)
#define BB      4     // batch rows per block
#define NTHREADS 416  // 104 n-slots * 4 kc (13 warps; n>=100 inert)
#define NBLOCKS  128
#define BTOT     512

typedef unsigned long long ull;

// Scratch for h history: [t][n][b]  (1024*100*512*4B ~= 210MB, static .bss)
__device__ float g_hscr[T_STEPS][Hn][BTOT];

// ---------- f32x2 packed-math helpers ----------
__device__ __forceinline__ ull pack2(float lo, float hi) {
    ull r; asm("mov.b64 %0, {%1, %2};" : "=l"(r) : "f"(lo), "f"(hi)); return r;
}
__device__ __forceinline__ void unpack2(ull v, float& lo, float& hi) {
    asm("mov.b64 {%0, %1}, %2;" : "=f"(lo), "=f"(hi) : "l"(v));
}
__device__ __forceinline__ ull ffma2(ull a, ull b, ull c) {
    ull d; asm("fma.rn.f32x2 %0, %1, %2, %3;" : "=l"(d) : "l"(a), "l"(b), "l"(c)); return d;
}
__device__ __forceinline__ ull fadd2(ull a, ull b) {
    ull d; asm("add.rn.f32x2 %0, %1, %2;" : "=l"(d) : "l"(a), "l"(b)); return d;
}

// ---------- fast transcendentals (MUFU, ~1e-6 rel err) ----------
__device__ __forceinline__ float ex2a(float x) {
    float y; asm("ex2.approx.ftz.f32 %0, %1;" : "=f"(y) : "f"(x)); return y;
}
__device__ __forceinline__ float rcpa(float x) {
    float y; asm("rcp.approx.ftz.f32 %0, %1;" : "=f"(y) : "f"(x)); return y;
}
__device__ __forceinline__ float sigm(float x) {
    return rcpa(1.0f + ex2a(-1.4426950408889634f * x));
}
__device__ __forceinline__ float tanhx(float x) {
    return fmaf(2.0f, rcpa(1.0f + ex2a(-2.8853900817779268f * x)), -1.0f);
}

// Interleaved h layout inside one batch row of 100 floats:
//   k = q*25 + r:  r<24: idx=(r/4)*16 + q*4 + (r%4);  r==24: idx=96+q.
// Thread kc=q reads 6 float4 at idx j*16+q*4 + 1 scalar at 96+q; the 4 q
// streams are adjacent 16B chunks -> broadcast-dedup to ~1 wavefront/LDS.
__device__ __forceinline__ int h_idx_of_k(int k) {
    int q = k / 25, r = k % 25;
    return (r < 24) ? ((r >> 2) * 16 + q * 4 + (r & 3)) : (96 + q);
}

// Thread layout: tid = n*4 + kc. Lane owns batch b = kc.
// 13 warps -> 4/SMSP -> hard cap 128 regs/thread.
__global__ void __launch_bounds__(NTHREADS, 1)
lstm_persistent_kernel(const float* __restrict__ input,   // [512][1024]
                       const float* __restrict__ W_ih,    // [400]
                       const float* __restrict__ W_hh,    // [400][100]
                       const float* __restrict__ b_ih,    // [400]
                       const float* __restrict__ b_hh)    // [400]
{
    __shared__ __align__(16) float h2[2][BB][HPAD];        // double buffered
    __shared__ __align__(16) ulonglong2 s_gp1[HPAD];       // {wih(i,f), bias(i,f)}
    __shared__ __align__(16) ulonglong2 s_gp2[HPAD];       // {wih(g,o), bias(g,o)}

    const int tid  = threadIdx.x;
    const int n    = tid >> 2;
    const int kc   = tid & 3;
    const int par  = kc & 1;
    const int side = kc >> 1;
    const bool valid = (n < Hn);
    const int bbase = blockIdx.x * BB;
    const int nsafe = valid ? n : 0;

    // ---- register-stationary recurrent weights: 48 ull pairs + 4 tails ----
    ull w[4][12]; float wt[4];
    #pragma unroll
    for (int g = 0; g < 4; ++g) {
        const float* row = W_hh + (g * Hn + nsafe) * Hn;
        #pragma unroll
        for (int j = 0; j < 12; ++j) {
            const int k0 = kc * 25 + 2 * j;
            w[g][j] = valid ? pack2(row[k0], row[k0 + 1]) : 0ULL;
        }
        wt[g] = valid ? row[kc * 25 + 24] : 0.0f;
    }
    // per-n wih/bias tables in SMEM (saves 8 persistent regs)
    if (kc == 0) {
        float wi = valid ? W_ih[n]            : 0.f;
        float wf = valid ? W_ih[Hn + n]       : 0.f;
        float wg = valid ? W_ih[2 * Hn + n]   : 0.f;
        float wo = valid ? W_ih[3 * Hn + n]   : 0.f;
        float bi = valid ? b_ih[n]          + b_hh[n]          : 0.f;
        float bf = valid ? b_ih[Hn + n]     + b_hh[Hn + n]     : 0.f;
        float bg = valid ? b_ih[2 * Hn + n] + b_hh[2 * Hn + n] : 0.f;
        float bo = valid ? b_ih[3 * Hn + n] + b_hh[3 * Hn + n] : 0.f;
        s_gp1[n] = make_ulonglong2(pack2(wi, wf), pack2(bi, bf));
        s_gp2[n] = make_ulonglong2(pack2(wg, wo), pack2(bg, bo));
    }

    for (int i = tid; i < 2 * BB * HPAD; i += NTHREADS)
        (&h2[0][0][0])[i] = 0.0f;

    float c_state = 0.0f;
    const float* __restrict__ xptr = input + (bbase + kc) * T_STEPS;
    // STS slot: valid -> interleaved slot of k=n; inert -> pad slots 100..103
    const int swidx = kc * HPAD + (valid ? h_idx_of_k(n) : (100 + (n - Hn)));
    float* __restrict__ sptr = &g_hscr[0][nsafe][bbase + kc];

    __syncthreads();

    for (int t = 0; t < T_STEPS; ++t) {
        const int p = t & 1;
        const float xv = xptr[t];
        const float* __restrict__ hb = &h2[p][0][0];

        ull G01 = 0ULL, G23 = 0ULL;
        #pragma unroll
        for (int half = 0; half < 2; ++half) {
            ull p01[2], p23[2];
            // one batch at a time: only 4 ull accumulators live
            #pragma unroll
            for (int bq = 0; bq < 2; ++bq) {
                const float* rowp = hb + (half * 2 + bq) * HPAD;
                const ulonglong2* v =
                    reinterpret_cast<const ulonglong2*>(rowp + kc * 4);
                ull a0 = 0, a1 = 0, a2 = 0, a3 = 0;
                #pragma unroll
                for (int j = 0; j < 6; ++j) {
                    const ulonglong2 hp = v[j * 4];
                    a0 = ffma2(w[0][2 * j], hp.x, a0);
                    a1 = ffma2(w[1][2 * j], hp.x, a1);
                    a2 = ffma2(w[2][2 * j], hp.x, a2);
                    a3 = ffma2(w[3][2 * j], hp.x, a3);
                    a0 = ffma2(w[0][2 * j + 1], hp.y, a0);
                    a1 = ffma2(w[1][2 * j + 1], hp.y, a1);
                    a2 = ffma2(w[2][2 * j + 1], hp.y, a2);
                    a3 = ffma2(w[3][2 * j + 1], hp.y, a3);
                }
                const float ht = rowp[96 + kc];
                float lo, hi, s0, s1, s2, s3;
                unpack2(a0, lo, hi); s0 = fmaf(wt[0], ht, lo + hi);
                unpack2(a1, lo, hi); s1 = fmaf(wt[1], ht, lo + hi);
                unpack2(a2, lo, hi); s2 = fmaf(wt[2], ht, lo + hi);
                unpack2(a3, lo, hi); s3 = fmaf(wt[3], ht, lo + hi);
                p01[bq] = pack2(s0, s1);
                p23[bq] = pack2(s2, s3);
            }
            // xor-1 first: exchange the partner's batch, keep own
            const ull t01 = par ? p01[0] : p01[1];
            const ull t23 = par ? p23[0] : p23[1];
            ull s01 = fadd2(par ? p01[1] : p01[0],
                            __shfl_xor_sync(0xffffffffu, t01, 1));
            ull s23 = fadd2(par ? p23[1] : p23[0],
                            __shfl_xor_sync(0xffffffffu, t23, 1));
            // xor-2: combine the two side-pairs
            s01 = fadd2(s01, __shfl_xor_sync(0xffffffffu, s01, 2));
            s23 = fadd2(s23, __shfl_xor_sync(0xffffffffu, s23, 2));
            if (side == half) { G01 = s01; G23 = s23; }
        }

        // ---- gates for (n, b = kc) ----
        const ulonglong2 gp1 = s_gp1[n];
        const ulonglong2 gp2 = s_gp2[n];
        const ull xv2 = pack2(xv, xv);
        G01 = ffma2(xv2, gp1.x, fadd2(G01, gp1.y));
        G23 = ffma2(xv2, gp2.x, fadd2(G23, gp2.y));
        float gi, gf, gg, go;
        unpack2(G01, gi, gf);
        unpack2(G23, gg, go);

        const float ig = sigm(gi);
        const float fg = sigm(gf);
        const float gc = tanhx(gg);
        const float og = sigm(go);
        c_state = fmaf(fg, c_state, ig * gc);
        const float h_ = og * tanhx(c_state);

        // publish h for next step (pad slot for inert lanes) + stream to gmem
        (&h2[0][0][0])[(p ^ 1) * (BB * HPAD) + swidx] = h_;
        if (valid) *sptr = h_;
        sptr += Hn * BTOT;

        __syncthreads();
    }
}

// Output projection: out[b][t] = sum_n W_out[n] * h[t][n][b] + b_out.
// Fully parallel, DRAM-bound (~210MB reads).
__global__ void __launch_bounds__(BTOT, 2)
out_proj_kernel(const float* __restrict__ W_out,
                const float* __restrict__ b_out,
                float* __restrict__ out)
{
    const int t = blockIdx.x;
    const int b = threadIdx.x;
    float acc = b_out[0];
    const float* __restrict__ hp = &g_hscr[t][0][b];
    #pragma unroll 5
    for (int nn = 0; nn < Hn; ++nn)
        acc = fmaf(W_out[nn], hp[(size_t)nn * BTOT], acc);
    out[b * T_STEPS + t] = acc;
}

extern "C" void kernel_launch(void* const* d_in, const int* in_sizes, int n_in,
                              void* d_out, int out_size) {
    (void)in_sizes; (void)n_in; (void)out_size;
    const float* input = (const float*)d_in[0];
    const float* W_ih  = (const float*)d_in[1];
    const float* W_hh  = (const float*)d_in[2];
    const float* b_ih  = (const float*)d_in[3];
    const float* b_hh  = (const float*)d_in[4];
    const float* W_out = (const float*)d_in[5];
    const float* b_out = (const float*)d_in[6];
    float* out = (float*)d_out;

    lstm_persistent_kernel<<<NBLOCKS, NTHREADS>>>(input, W_ih, W_hh, b_ih, b_hh);
    out_proj_kernel<<<T_STEPS, BTOT>>>(W_out, b_out, out);
}

// round 8
// speedup vs baseline: 1.4011x; 1.0029x over previous
#include <cuda_runtime.h>

// Problem constants
#define T_STEPS 1024
#define Hn      100
#define HPAD    128   // padded hidden row (pow-2 stride; 28 pad slots)
#define BB      4     // batch rows per block
#define NTHREADS 512  // 128 n-slots * 4 kc (16 warps, 4/SMSP even)
#define NWARPS  16
#define NBLOCKS  128
#define BTOT     512

typedef unsigned long long ull;

// Scratch for h history: [t][n][b]  (1024*100*512*4B ~= 210MB, static .bss)
__device__ float g_hscr[T_STEPS][Hn][BTOT];

// ---------- f32x2 packed-math helpers ----------
__device__ __forceinline__ ull pack2(float lo, float hi) {
    ull r; asm("mov.b64 %0, {%1, %2};" : "=l"(r) : "f"(lo), "f"(hi)); return r;
}
__device__ __forceinline__ void unpack2(ull v, float& lo, float& hi) {
    asm("mov.b64 {%0, %1}, %2;" : "=f"(lo), "=f"(hi) : "l"(v));
}
__device__ __forceinline__ ull ffma2(ull a, ull b, ull c) {
    ull d; asm("fma.rn.f32x2 %0, %1, %2, %3;" : "=l"(d) : "l"(a), "l"(b), "l"(c)); return d;
}
__device__ __forceinline__ ull fadd2(ull a, ull b) {
    ull d; asm("add.rn.f32x2 %0, %1, %2;" : "=l"(d) : "l"(a), "l"(b)); return d;
}

// ---------- fast transcendentals (MUFU, ~1e-6 rel err) ----------
__device__ __forceinline__ float ex2a(float x) {
    float y; asm("ex2.approx.ftz.f32 %0, %1;" : "=f"(y) : "f"(x)); return y;
}
__device__ __forceinline__ float rcpa(float x) {
    float y; asm("rcp.approx.ftz.f32 %0, %1;" : "=f"(y) : "f"(x)); return y;
}
__device__ __forceinline__ float sigm(float x) {
    return rcpa(1.0f + ex2a(-1.4426950408889634f * x));
}
__device__ __forceinline__ float tanhx(float x) {
    return fmaf(2.0f, rcpa(1.0f + ex2a(-2.8853900817779268f * x)), -1.0f);
}

// Interleaved h layout inside one batch row (valid k packed into idx 0..99):
//   k = q*25 + r:  r<24: idx=(r/4)*16 + q*4 + (r%4);  r==24: idx=96+q.
// Thread kc=q reads 6 float4 at idx j*16+q*4 + 1 scalar at 96+q; the 4 q
// streams are adjacent 16B chunks -> broadcast-dedup to ~1 wavefront/LDS.
__device__ __forceinline__ int h_idx_of_k(int k) {
    int q = k / 25, r = k % 25;
    return (r < 24) ? ((r >> 2) * 16 + q * 4 + (r & 3)) : (96 + q);
}

// Thread layout: tid = n*4 + kc, n in [0,128) (n>=100 inert, zero weights).
// Lane owns batch b = kc after the in-warp reduction (c-state in a register).
// 16 warps -> 4/SMSP even -> reg cap 128/thread; ~17 read-only weight regs
// spill (coalesced LDL reloads) — structurally unavoidable at this width.
__global__ void __launch_bounds__(NTHREADS, 1)
lstm_persistent_kernel(const float* __restrict__ input,   // [512][1024]
                       const float* __restrict__ W_ih,    // [400]
                       const float* __restrict__ W_hh,    // [400][100]
                       const float* __restrict__ b_ih,    // [400]
                       const float* __restrict__ b_hh)    // [400]
{
    __shared__ __align__(16) float h2[2][BB][HPAD];        // double buffered
    __shared__ __align__(16) ulonglong2 s_gp1[HPAD];       // {wih(i,f), bias(i,f)}
    __shared__ __align__(16) ulonglong2 s_gp2[HPAD];       // {wih(g,o), bias(g,o)}

    const int tid  = threadIdx.x;
    const int n    = tid >> 2;
    const int kc   = tid & 3;
    const int par  = kc & 1;
    const int side = kc >> 1;
    const bool valid = (n < Hn);
    const int bbase = blockIdx.x * BB;
    const int nsafe = valid ? n : 0;

    // ---- register-stationary recurrent weights: 48 ull pairs + 4 tails ----
    ull w[4][12]; float wt[4];
    #pragma unroll
    for (int g = 0; g < 4; ++g) {
        const float* row = W_hh + (g * Hn + nsafe) * Hn;
        #pragma unroll
        for (int j = 0; j < 12; ++j) {
            const int k0 = kc * 25 + 2 * j;
            w[g][j] = valid ? pack2(row[k0], row[k0 + 1]) : 0ULL;
        }
        wt[g] = valid ? row[kc * 25 + 24] : 0.0f;
    }
    // per-n wih/bias tables in SMEM (saves 8 persistent regs)
    if (kc == 0) {
        float wi = valid ? W_ih[n]            : 0.f;
        float wf = valid ? W_ih[Hn + n]       : 0.f;
        float wg = valid ? W_ih[2 * Hn + n]   : 0.f;
        float wo = valid ? W_ih[3 * Hn + n]   : 0.f;
        float bi = valid ? b_ih[n]          + b_hh[n]          : 0.f;
        float bf = valid ? b_ih[Hn + n]     + b_hh[Hn + n]     : 0.f;
        float bg = valid ? b_ih[2 * Hn + n] + b_hh[2 * Hn + n] : 0.f;
        float bo = valid ? b_ih[3 * Hn + n] + b_hh[3 * Hn + n] : 0.f;
        s_gp1[n] = make_ulonglong2(pack2(wi, wf), pack2(bi, bf));
        s_gp2[n] = make_ulonglong2(pack2(wg, wo), pack2(bg, bo));
    }

    for (int i = tid; i < 2 * BB * HPAD; i += NTHREADS)
        (&h2[0][0][0])[i] = 0.0f;

    float c_state = 0.0f;
    const float* __restrict__ xptr = input + (bbase + kc) * T_STEPS;
    // STS slot: valid -> interleaved slot of k=n; inert -> pad slots 100..127
    const int swidx = kc * HPAD + (valid ? h_idx_of_k(n) : n);
    float* __restrict__ sptr = &g_hscr[0][nsafe][bbase + kc];

    __syncthreads();

    for (int t = 0; t < T_STEPS; ++t) {
        const int p = t & 1;
        const float xv = xptr[t];
        const float* __restrict__ hb = &h2[p][0][0];

        ull G01 = 0ULL, G23 = 0ULL;
        #pragma unroll
        for (int half = 0; half < 2; ++half) {
            ull p01[2], p23[2];
            // one batch at a time: only 4 ull accumulators live
            #pragma unroll
            for (int bq = 0; bq < 2; ++bq) {
                const float* rowp = hb + (half * 2 + bq) * HPAD;
                const ulonglong2* v =
                    reinterpret_cast<const ulonglong2*>(rowp + kc * 4);
                ull a0 = 0, a1 = 0, a2 = 0, a3 = 0;
                #pragma unroll
                for (int j = 0; j < 6; ++j) {
                    const ulonglong2 hp = v[j * 4];
                    a0 = ffma2(w[0][2 * j], hp.x, a0);
                    a1 = ffma2(w[1][2 * j], hp.x, a1);
                    a2 = ffma2(w[2][2 * j], hp.x, a2);
                    a3 = ffma2(w[3][2 * j], hp.x, a3);
                    a0 = ffma2(w[0][2 * j + 1], hp.y, a0);
                    a1 = ffma2(w[1][2 * j + 1], hp.y, a1);
                    a2 = ffma2(w[2][2 * j + 1], hp.y, a2);
                    a3 = ffma2(w[3][2 * j + 1], hp.y, a3);
                }
                const float ht = rowp[96 + kc];
                float lo, hi, s0, s1, s2, s3;
                unpack2(a0, lo, hi); s0 = fmaf(wt[0], ht, lo + hi);
                unpack2(a1, lo, hi); s1 = fmaf(wt[1], ht, lo + hi);
                unpack2(a2, lo, hi); s2 = fmaf(wt[2], ht, lo + hi);
                unpack2(a3, lo, hi); s3 = fmaf(wt[3], ht, lo + hi);
                p01[bq] = pack2(s0, s1);
                p23[bq] = pack2(s2, s3);
            }
            // xor-1 first: exchange the partner's batch, keep own
            const ull t01 = par ? p01[0] : p01[1];
            const ull t23 = par ? p23[0] : p23[1];
            ull s01 = fadd2(par ? p01[1] : p01[0],
                            __shfl_xor_sync(0xffffffffu, t01, 1));
            ull s23 = fadd2(par ? p23[1] : p23[0],
                            __shfl_xor_sync(0xffffffffu, t23, 1));
            // xor-2: combine the two side-pairs
            s01 = fadd2(s01, __shfl_xor_sync(0xffffffffu, s01, 2));
            s23 = fadd2(s23, __shfl_xor_sync(0xffffffffu, s23, 2));
            if (side == half) { G01 = s01; G23 = s23; }
        }

        // ---- gates for (n, b = kc) ----
        const ulonglong2 gp1 = s_gp1[n];
        const ulonglong2 gp2 = s_gp2[n];
        const ull xv2 = pack2(xv, xv);
        G01 = ffma2(xv2, gp1.x, fadd2(G01, gp1.y));
        G23 = ffma2(xv2, gp2.x, fadd2(G23, gp2.y));
        float gi, gf, gg, go;
        unpack2(G01, gi, gf);
        unpack2(G23, gg, go);

        const float ig = sigm(gi);
        const float fg = sigm(gf);
        const float gc = tanhx(gg);
        const float og = sigm(go);
        c_state = fmaf(fg, c_state, ig * gc);
        const float h_ = og * tanhx(c_state);

        // publish h for next step (pad slot for inert lanes) + stream to gmem
        (&h2[0][0][0])[(p ^ 1) * (BB * HPAD) + swidx] = h_;
        if (valid) *sptr = h_;
        sptr += Hn * BTOT;

        __syncthreads();
    }
}

// Output projection: out[b][t] = sum_n W_out[n] * h[t][n][b] + b_out.
// Fully parallel, DRAM-bound (~210MB reads).
__global__ void __launch_bounds__(BTOT, 2)
out_proj_kernel(const float* __restrict__ W_out,
                const float* __restrict__ b_out,
                float* __restrict__ out)
{
    const int t = blockIdx.x;
    const int b = threadIdx.x;
    float acc = b_out[0];
    const float* __restrict__ hp = &g_hscr[t][0][b];
    #pragma unroll 5
    for (int nn = 0; nn < Hn; ++nn)
        acc = fmaf(W_out[nn], hp[(size_t)nn * BTOT], acc);
    out[b * T_STEPS + t] = acc;
}

extern "C" void kernel_launch(void* const* d_in, const int* in_sizes, int n_in,
                              void* d_out, int out_size) {
    (void)in_sizes; (void)n_in; (void)out_size;
    const float* input = (const float*)d_in[0];
    const float* W_ih  = (const float*)d_in[1];
    const float* W_hh  = (const float*)d_in[2];
    const float* b_ih  = (const float*)d_in[3];
    const float* b_hh  = (const float*)d_in[4];
    const float* W_out = (const float*)d_in[5];
    const float* b_out = (const float*)d_in[6];
    float* out = (float*)d_out;

    lstm_persistent_kernel<<<NBLOCKS, NTHREADS>>>(input, W_ih, W_hh, b_ih, b_hh);
    out_proj_kernel<<<T_STEPS, BTOT>>>(W_out, b_out, out);
}

// round 12
// speedup vs baseline: 1.6718x; 1.1932x over previous
#include <cuda_runtime.h>
#include <cstdint>

// Problem constants
#define T_STEPS 1024
#define Hn      100
#define HROW    128   // padded h row stride (slots 0..99 valid, 100..127 pad)
#define BB      4     // batch rows per block
#define NTHREADS 256  // 128 ln-slots * 2 kc (8 warps, 2/SMSP -> reg cap 256)
#define NBLOCKS  128  // 128 blocks * 4 batches = all 512 batches (R9-R11 bug:
                      // cluster variant covered only 256 of 512)
#define BTOT     512

typedef unsigned long long ull;

// Scratch for h history: [t][n][b]  (~210MB, static .bss)
__device__ float g_hscr[T_STEPS][Hn][BTOT];

// ---------- f32x2 packed-math helpers ----------
__device__ __forceinline__ ull pack2(float lo, float hi) {
    ull r; asm("mov.b64 %0, {%1, %2};" : "=l"(r) : "f"(lo), "f"(hi)); return r;
}
__device__ __forceinline__ void unpack2(ull v, float& lo, float& hi) {
    asm("mov.b64 {%0, %1}, %2;" : "=f"(lo), "=f"(hi) : "l"(v));
}
__device__ __forceinline__ ull ffma2(ull a, ull b, ull c) {
    ull d; asm("fma.rn.f32x2 %0, %1, %2, %3;" : "=l"(d) : "l"(a), "l"(b), "l"(c)); return d;
}
__device__ __forceinline__ ull fadd2(ull a, ull b) {
    ull d; asm("add.rn.f32x2 %0, %1, %2;" : "=l"(d) : "l"(a), "l"(b)); return d;
}

// ---------- fast transcendentals (MUFU, ~1e-6 rel err) ----------
__device__ __forceinline__ float ex2a(float x) {
    float y; asm("ex2.approx.ftz.f32 %0, %1;" : "=f"(y) : "f"(x)); return y;
}
__device__ __forceinline__ float rcpa(float x) {
    float y; asm("rcp.approx.ftz.f32 %0, %1;" : "=f"(y) : "f"(x)); return y;
}
__device__ __forceinline__ float sigm(float x) {
    return rcpa(1.0f + ex2a(-1.4426950408889634f * x));
}
__device__ __forceinline__ float tanhx(float x) {
    return fmaf(2.0f, rcpa(1.0f + ex2a(-2.8853900817779268f * x)), -1.0f);
}

// Interleaved h layout inside one batch row (valid k packed into idx 0..99):
//   k = q*50 + r (q = k-half 0/1):
//     r < 48 : idx = (r/4)*8 + q*4 + (r%4)   (12 float4 chunks per half)
//     r >= 48: idx = 96 + q*2 + (r-48)        (float2 tail)
// => thread kc=q reads 12 float4 at idx j*8+q*4 plus 1 float2 at 96+q*2.
//    Within one warp the 2 q streams at the same j are ADJACENT 16B chunks
//    (one 32B run) and all ln broadcast -> ~1 wavefront per LDS.
__device__ __forceinline__ int h_idx_of_k(int k) {
    int q = k / 50, r = k % 50;
    return (r < 48) ? ((r >> 2) * 8 + q * 4 + (r & 3)) : (96 + q * 2 + (r - 48));
}

// Thread layout: tid = ln*2 + kc, ln in [0,128) (ln>=100 inert), kc = k-half.
// After the single xor-1 reduction, lane kc owns batches {2kc, 2kc+1}
// (two c-states in registers).
// 8 warps -> 2/SMSP -> reg cap 256: all 200 weight regs resident, NO spills.
// Warp 7 (ln 112..127, fully inert) skips the compute body entirely.
__global__ void __launch_bounds__(NTHREADS, 1)
lstm_persistent_kernel(const float* __restrict__ input,   // [512][1024]
                       const float* __restrict__ W_ih,    // [400]
                       const float* __restrict__ W_hh,    // [400][100]
                       const float* __restrict__ b_ih,    // [400]
                       const float* __restrict__ b_hh)    // [400]
{
    __shared__ __align__(16) float h2[2][BB][HROW];        // double buffered
    __shared__ __align__(16) ulonglong2 s_gp1[128];        // {wih(i,f), bias(i,f)}
    __shared__ __align__(16) ulonglong2 s_gp2[128];        // {wih(g,o), bias(g,o)}

    const int tid  = threadIdx.x;
    const int ln   = tid >> 1;
    const int kc   = tid & 1;
    const bool valid = (ln < Hn);
    const int n = ln;
    const int nsafe = valid ? n : 0;
    const int bbase = blockIdx.x * BB;

    // ---- register-stationary weights: 25 k-pairs per gate (50 = 2*25) ----
    ull w[4][25];
    #pragma unroll
    for (int g = 0; g < 4; ++g) {
        const float* row = W_hh + (g * Hn + nsafe) * Hn;
        #pragma unroll
        for (int j = 0; j < 25; ++j) {
            const int k0 = kc * 50 + 2 * j;
            w[g][j] = valid ? pack2(row[k0], row[k0 + 1]) : 0ULL;
        }
    }
    // per-n wih/bias tables in SMEM
    if (kc == 0) {
        float wi = valid ? W_ih[n]            : 0.f;
        float wf = valid ? W_ih[Hn + n]       : 0.f;
        float wg = valid ? W_ih[2 * Hn + n]   : 0.f;
        float wo = valid ? W_ih[3 * Hn + n]   : 0.f;
        float bi = valid ? b_ih[n]          + b_hh[n]          : 0.f;
        float bf = valid ? b_ih[Hn + n]     + b_hh[Hn + n]     : 0.f;
        float bg = valid ? b_ih[2 * Hn + n] + b_hh[2 * Hn + n] : 0.f;
        float bo = valid ? b_ih[3 * Hn + n] + b_hh[3 * Hn + n] : 0.f;
        s_gp1[ln] = make_ulonglong2(pack2(wi, wf), pack2(bi, bf));
        s_gp2[ln] = make_ulonglong2(pack2(wg, wo), pack2(bg, bo));
    }

    // zero both h buffers
    for (int i = tid; i < 2 * BB * HROW; i += NTHREADS)
        (&h2[0][0][0])[i] = 0.0f;

    float c0 = 0.0f, c1 = 0.0f;     // c-states for owned batches 2kc, 2kc+1
    const float* __restrict__ xptrA = input + (bbase + 2 * kc) * T_STEPS;
    const float* __restrict__ xptrB = xptrA + T_STEPS;
    // h write slot: valid -> interleaved slot of k=n; inert (warp6) -> pad ln
    const int widx = valid ? h_idx_of_k(n) : ln;   // pads 100..111 for warp 6
    // h history: batches 2kc, 2kc+1 adjacent -> one STG.64
    float* __restrict__ sptr = &g_hscr[0][nsafe][bbase + 2 * kc];

    __syncthreads();

    for (int t = 0; t < T_STEPS; ++t) {
        const int p = t & 1;
        if (ln < 112) {   // warp 7 fully inert: skip body, keep barrier
            const float xa = xptrA[t];
            const float xb = xptrB[t];
            const float* __restrict__ hb = &h2[p][0][0];

            ull G01[2], G23[2];
            #pragma unroll
            for (int b = 0; b < BB; ++b) {
                const float* rowp = hb + b * HROW;
                const ulonglong2* v =
                    reinterpret_cast<const ulonglong2*>(rowp + kc * 4);
                ull a0 = 0, a1 = 0, a2 = 0, a3 = 0;
                #pragma unroll
                for (int j = 0; j < 12; ++j) {
                    const ulonglong2 hp = v[j * 2];   // k-pairs 2j, 2j+1
                    a0 = ffma2(w[0][2 * j], hp.x, a0);
                    a1 = ffma2(w[1][2 * j], hp.x, a1);
                    a2 = ffma2(w[2][2 * j], hp.x, a2);
                    a3 = ffma2(w[3][2 * j], hp.x, a3);
                    a0 = ffma2(w[0][2 * j + 1], hp.y, a0);
                    a1 = ffma2(w[1][2 * j + 1], hp.y, a1);
                    a2 = ffma2(w[2][2 * j + 1], hp.y, a2);
                    a3 = ffma2(w[3][2 * j + 1], hp.y, a3);
                }
                // tail k-pair (r = 48,49) at idx 96 + kc*2
                const ull ht = *reinterpret_cast<const ull*>(rowp + 96 + kc * 2);
                a0 = ffma2(w[0][24], ht, a0);
                a1 = ffma2(w[1][24], ht, a1);
                a2 = ffma2(w[2][24], ht, a2);
                a3 = ffma2(w[3][24], ht, a3);
                // fold k-pair lanes, pack by gate pairs
                float lo, hi, s0, s1, s2, s3;
                unpack2(a0, lo, hi); s0 = lo + hi;
                unpack2(a1, lo, hi); s1 = lo + hi;
                unpack2(a2, lo, hi); s2 = lo + hi;
                unpack2(a3, lo, hi); s3 = lo + hi;
                const ull p01 = pack2(s0, s1);
                const ull p23 = pack2(s2, s3);
                // single xor-1 exchange with the other k-half
                const ull r01 = __shfl_xor_sync(0xffffffffu, p01, 1);
                const ull r23 = __shfl_xor_sync(0xffffffffu, p23, 1);
                if ((b >> 1) == kc) {
                    G01[b & 1] = fadd2(p01, r01);
                    G23[b & 1] = fadd2(p23, r23);
                }
            }

            // ---- elementwise for owned batches (n, 2kc) and (n, 2kc+1) ----
            const ulonglong2 gp1 = s_gp1[ln];
            const ulonglong2 gp2 = s_gp2[ln];
            float h0, h1;
            {
                const ull xv2 = pack2(xa, xa);
                const ull A = ffma2(xv2, gp1.x, fadd2(G01[0], gp1.y));
                const ull B = ffma2(xv2, gp2.x, fadd2(G23[0], gp2.y));
                float gi, gf, gg, go;
                unpack2(A, gi, gf); unpack2(B, gg, go);
                c0 = fmaf(sigm(gf), c0, sigm(gi) * tanhx(gg));
                h0 = sigm(go) * tanhx(c0);
            }
            {
                const ull xv2 = pack2(xb, xb);
                const ull A = ffma2(xv2, gp1.x, fadd2(G01[1], gp1.y));
                const ull B = ffma2(xv2, gp2.x, fadd2(G23[1], gp2.y));
                float gi, gf, gg, go;
                unpack2(A, gi, gf); unpack2(B, gg, go);
                c1 = fmaf(sigm(gf), c1, sigm(gi) * tanhx(gg));
                h1 = sigm(go) * tanhx(c1);
            }

            // publish h into next buffer (rows = owned batches)
            float* hw = &h2[p ^ 1][0][0];
            hw[(2 * kc)     * HROW + widx] = h0;
            hw[(2 * kc + 1) * HROW + widx] = h1;
            // stream h history: one STG.64 (adjacent batches)
            if (valid)
                *reinterpret_cast<ull*>(sptr) = pack2(h0, h1);
            sptr += Hn * BTOT;
        }
        __syncthreads();
    }
}

// Output projection: out[b][t] = sum_n W_out[n] * h[t][n][b] + b_out.
// Fully parallel, DRAM-bound (~210MB reads, measured 40us @ 67% DRAM).
__global__ void __launch_bounds__(BTOT, 2)
out_proj_kernel(const float* __restrict__ W_out,
                const float* __restrict__ b_out,
                float* __restrict__ out)
{
    const int t = blockIdx.x;
    const int b = threadIdx.x;
    float acc = b_out[0];
    const float* __restrict__ hp = &g_hscr[t][0][b];
    #pragma unroll 5
    for (int nn = 0; nn < Hn; ++nn)
        acc = fmaf(W_out[nn], hp[(size_t)nn * BTOT], acc);
    out[b * T_STEPS + t] = acc;
}

extern "C" void kernel_launch(void* const* d_in, const int* in_sizes, int n_in,
                              void* d_out, int out_size) {
    (void)in_sizes; (void)n_in; (void)out_size;
    const float* input = (const float*)d_in[0];
    const float* W_ih  = (const float*)d_in[1];
    const float* W_hh  = (const float*)d_in[2];
    const float* b_ih  = (const float*)d_in[3];
    const float* b_hh  = (const float*)d_in[4];
    const float* W_out = (const float*)d_in[5];
    const float* b_out = (const float*)d_in[6];
    float* out = (float*)d_out;

    lstm_persistent_kernel<<<NBLOCKS, NTHREADS>>>(input, W_ih, W_hh, b_ih, b_hh);
    out_proj_kernel<<<T_STEPS, BTOT>>>(W_out, b_out, out);
}